// round 10
// baseline (speedup 1.0000x reference)
#include <cuda_runtime.h>
#include <math.h>
#include <stdint.h>

// Problem constants (fixed shapes from setup_inputs)
#define BB 8
#define CC 5
#define HH 768
#define WW 768
#define HW (HH*WW)
#define NPIX (BB*HW)          // 4,718,592
#define NV4  (NPIX/4)         // 1,179,648
#define HWV4 (HW/4)           // 147,456
#define NTC 4

#define EPSF 1e-7f
#define ONEMF ((float)(1.0 - 1e-7))

// strips for local CCL
#define SH 8
#define SPIX (SH*WW)              // 6144
#define STRIPS_PER_IMG (HH/SH)    // 96
#define NSTRIP (BB*STRIPS_PER_IMG)// 768
#define NEDGE (BB*(STRIPS_PER_IMG-1)*WW)  // 583,680
#define SLOTS 1536                        // border slots per strip (2*WW)
#define NSLOT (NSTRIP*SLOTS)              // 1,179,648  (< 2^23)

// ---------------- static device scratch ----------------
__device__ __align__(16) unsigned char g_pm[NPIX]; // argmax class per pixel
__device__ int           g_uf[NSLOT];       // compact global UF over border slots (4.7MB)
__device__ int           g_btop[NSTRIP*WW]; // packed rep-slot of top-row pixels (-1 = bg)
__device__ int           g_bbot[NSTRIP*WW]; // packed rep-slot of bottom-row pixels
__device__ double        g_acc[4][20];      // [stat][cell]: 1=spho 2=slog 3=sl1p (0 unused)
__device__ int           g_cnt[20];         // exact joint counts [tm][pm]
__device__ int           g_lroots[4];       // Σ run-starts per class 1..4
__device__ int           g_merged[4];       // Σ successful UF links (in-strip + cross-strip)

// ---------------- K0: zero accumulators ----------------
__global__ void k_zero() {
    int t = threadIdx.x;
    if (t < 80) ((double*)g_acc)[t] = 0.0;
    if (t < 20) g_cnt[t] = 0;
    if (t < 4) { g_lroots[t] = 0; g_merged[t] = 0; }
}

// ---------------- K1: argmax + joint stats ----------------
// 888 blocks = 6/SM x 148 SMs (exact capacity, single wave). Slab 30KB (3 float stats);
// counts live in packed per-thread registers (1 byte per cell, <=44 pixels/thread).
__global__ void __launch_bounds__(128, 6) k_stats(const float* __restrict__ pred,
                                                  const int*   __restrict__ tmask) {
    __shared__ float slab[4][3][20][32];   // [warp][stat][cell][lane] — bank-conflict free
    __shared__ int s_cnt[20];
    const int tid  = threadIdx.x;
    const int warp = tid >> 5, lane = tid & 31;
    for (int k = tid; k < 4*3*20*32; k += 128) ((float*)slab)[k] = 0.f;
    if (tid < 20) s_cnt[tid] = 0;
    __syncthreads();

    float* my = &slab[warp][0][0][lane];
    unsigned int pc[5] = {0u, 0u, 0u, 0u, 0u};   // packed byte counters for 20 cells

    const int stride = gridDim.x * 128;
    for (int v = blockIdx.x * 128 + tid; v < NV4; v += stride) {
        int img = v / HWV4;
        int vin = v - img * HWV4;
        const float* pb = pred + (size_t)img * CC * HW;
        int j = vin * 4;
        float4 c0 = *(const float4*)(pb + j);
        float4 c1 = *(const float4*)(pb + HW + j);
        float4 c2 = *(const float4*)(pb + 2*HW + j);
        float4 c3 = *(const float4*)(pb + 3*HW + j);
        float4 c4 = *(const float4*)(pb + 4*HW + j);
        int4  tv  = ((const int4*)tmask)[v];

        float A0[4] = {c0.x, c0.y, c0.z, c0.w};
        float A1[4] = {c1.x, c1.y, c1.z, c1.w};
        float A2[4] = {c2.x, c2.y, c2.z, c2.w};
        float A3[4] = {c3.x, c3.y, c3.z, c3.w};
        float A4[4] = {c4.x, c4.y, c4.z, c4.w};
        int tvv[4] = {tv.x, tv.y, tv.z, tv.w};
        unsigned char bcs[4];

        #pragma unroll
        for (int e = 0; e < 4; e++) {
            float best = A0[e]; int bc = 0;
            if (A1[e] > best) { best = A1[e]; bc = 1; }
            if (A2[e] > best) { best = A2[e]; bc = 2; }
            if (A3[e] > best) { best = A3[e]; bc = 3; }
            if (A4[e] > best) { best = A4[e]; bc = 4; }
            bcs[e] = (unsigned char)bc;

            int t = tvv[e]; t = t < 0 ? 0 : (t > 3 ? 3 : t);
            int cell = t * 5 + bc;
            pc[cell >> 2] += 1u << ((cell & 3) * 8);

            float q  = bc ? best : 0.0f;
            float qc = fminf(fmaxf(q, EPSF), ONEMF);
            float lg = __logf(qc);
            float l1 = __logf(1.0f - qc);
            float* p = my + cell * 32;
            p[0]    += q;
            p[640]  += lg;
            p[1280] += l1;
        }
        ((uchar4*)g_pm)[v] = make_uchar4(bcs[0], bcs[1], bcs[2], bcs[3]);
    }

    #pragma unroll
    for (int k = 0; k < 5; k++) {
        unsigned x = pc[k];
        unsigned lo = __reduce_add_sync(0xFFFFFFFFu, x & 0x00FF00FFu);
        unsigned hi = __reduce_add_sync(0xFFFFFFFFu, (x >> 8) & 0x00FF00FFu);
        if (lane == 0) {
            if (lo & 0xFFFFu) atomicAdd(&s_cnt[k*4 + 0], (int)(lo & 0xFFFFu));
            if (lo >> 16)     atomicAdd(&s_cnt[k*4 + 2], (int)(lo >> 16));
            if (hi & 0xFFFFu) atomicAdd(&s_cnt[k*4 + 1], (int)(hi & 0xFFFFu));
            if (hi >> 16)     atomicAdd(&s_cnt[k*4 + 3], (int)(hi >> 16));
        }
    }
    __syncthreads();

    if (tid < 60) {
        int s = tid / 20, c = tid % 20;
        double acc = 0.0;
        #pragma unroll
        for (int w = 0; w < 4; w++)
            for (int l = 0; l < 32; l++) acc += (double)slab[w][s][c][l];
        atomicAdd(&g_acc[s + 1][c], acc);
    }
    if (tid < 20 && s_cnt[tid]) atomicAdd(&g_cnt[tid], s_cnt[tid]);
}

// ---------------- shared-memory union-find (monotone links, race-safe compression) ----------------
// Invariant: every write lab[c] = y has y < c (strictly decreasing links). The
// compression write is guarded (n > r) so a concurrent deeper compression can
// never induce an upward link (the R8/R9 hang).
__device__ __forceinline__ int find_s(int* lab, int x) {
    int r = x, l = lab[r];
    while (l != r) { r = l; l = lab[r]; }
    int c = x;
    while (c > r) {
        int n = lab[c];
        if (n <= r) break;      // at/below root already — do not write upward
        lab[c] = r;             // c > n > r  => monotone preserved
        c = n;
    }
    return r;
}
__device__ __forceinline__ bool union_s(int* lab, int a, int b) {
    while (true) {
        a = find_s(lab, a); b = find_s(lab, b);
        if (a == b) return false;
        if (a < b) { int t = a; a = b; b = t; }
        int old = atomicCAS(&lab[a], a, b);
        if (old == a) return true;     // exactly one root retired
        a = old;
    }
}

// ---------------- K2: per-strip CCL (SIMD-in-word passes) ----------------
__global__ void __launch_bounds__(256) k_ccl() {
    __shared__ int lab[SPIX];                 // 24KB (repurposed as minpos in export)
    __shared__ unsigned char pm[SPIX];        // 6KB
    __shared__ unsigned short rootof[SLOTS];  // 3KB
    __shared__ int rc8[8];                    // [0..3]=runs, [4..7]=vsucc
    const int tid = threadIdx.x;
    const int lane = tid & 31;
    const int strip = blockIdx.x;
    const int base = strip * SPIX;
    const unsigned* pmw = (const unsigned*)pm;

    for (int v = tid; v < SPIX/16; v += 256)
        ((int4*)pm)[v] = ((const int4*)(g_pm + base))[v];
    if (tid < 8) rc8[tid] = 0;
    __syncthreads();

    // Pass A: word-parallel horizontal chains + per-class run counts (x8 via popc)
    int rr1 = 0, rr2 = 0, rr3 = 0, rr4 = 0;
    for (int v = tid; v < SPIX/4; v += 256) {
        unsigned c = pmw[v];
        unsigned prev = (v % (WW/4)) ? pmw[v - 1] : 0xFFFFFFFFu;
        unsigned left = (c << 8) | (prev >> 24);
        unsigned nz   = __vcmpne4(c, 0u);
        unsigned runm = __vcmpne4(c, left) & nz;
        unsigned cont = nz & ~runm;            // c!=0 && c==left : link to j-1
        int j = v * 4;
        int4 L;
        L.x = j     - (int)( cont        & 1u);
        L.y = j + 1 - (int)((cont >> 8)  & 1u);
        L.z = j + 2 - (int)((cont >> 16) & 1u);
        L.w = j + 3 - (int)((cont >> 24) & 1u);
        ((int4*)lab)[v] = L;
        rr1 += __popc(runm & __vcmpeq4(c, 0x01010101u));
        rr2 += __popc(runm & __vcmpeq4(c, 0x02020202u));
        rr3 += __popc(runm & __vcmpeq4(c, 0x03030303u));
        rr4 += __popc(runm & __vcmpeq4(c, 0x04040404u));
    }
    __syncthreads();

    // Pass B: word-parallel vertical match detection, sparse unions
    unsigned pv = 0u;   // packed per-class success counts, byte (cls-1)
    for (int wv = tid; wv < (SPIX - WW)/4; wv += 256) {
        int v = wv + WW/4;
        unsigned c  = pmw[v];
        unsigned up = pmw[v - WW/4];
        unsigned m = __vcmpeq4(c, up) & __vcmpne4(c, 0u);
        while (m) {
            int b = __ffs(m) - 1;
            int e = b >> 3;
            int j = v * 4 + e;
            if (union_s(lab, j, j - WW)) {
                unsigned cls = (c >> (e * 8)) & 0xFFu;
                pv += 1u << ((cls - 1) * 8);
            }
            m &= ~(0xFFu << (e * 8));
        }
    }
    // reduce counters
    {
        int s;
        s = __reduce_add_sync(0xFFFFFFFFu, rr1); if (lane==0 && s) atomicAdd(&rc8[0], s >> 3);
        s = __reduce_add_sync(0xFFFFFFFFu, rr2); if (lane==0 && s) atomicAdd(&rc8[1], s >> 3);
        s = __reduce_add_sync(0xFFFFFFFFu, rr3); if (lane==0 && s) atomicAdd(&rc8[2], s >> 3);
        s = __reduce_add_sync(0xFFFFFFFFu, rr4); if (lane==0 && s) atomicAdd(&rc8[3], s >> 3);
        unsigned lo = __reduce_add_sync(0xFFFFFFFFu, pv & 0x00FF00FFu);
        unsigned hi = __reduce_add_sync(0xFFFFFFFFu, (pv >> 8) & 0x00FF00FFu);
        if (lane == 0) {
            if (lo & 0xFFFFu) atomicAdd(&rc8[4], (int)(lo & 0xFFFFu));
            if (lo >> 16)     atomicAdd(&rc8[6], (int)(lo >> 16));
            if (hi & 0xFFFFu) atomicAdd(&rc8[5], (int)(hi & 0xFFFFu));
            if (hi >> 16)     atomicAdd(&rc8[7], (int)(hi >> 16));
        }
    }
    __syncthreads();

    // Pass C: export borders.
    for (int bp = tid; bp < SLOTS; bp += 256) {
        int j = (bp < WW) ? bp : (SPIX - WW) + (bp - WW);
        rootof[bp] = pm[j] ? (unsigned short)find_s(lab, j) : (unsigned short)0xFFFF;
    }
    __syncthreads();
    for (int v = tid; v < SPIX/4; v += 256)
        ((int4*)lab)[v] = make_int4(0x7FFFFFFF, 0x7FFFFFFF, 0x7FFFFFFF, 0x7FFFFFFF);
    __syncthreads();
    for (int bp = tid; bp < SLOTS; bp += 256) {
        unsigned short r = rootof[bp];
        if (r != 0xFFFF) atomicMin(&lab[r], bp);
    }
    __syncthreads();
    for (int bp = tid; bp < SLOTS; bp += 256) {
        int j = (bp < WW) ? bp : (SPIX - WW) + (bp - WW);
        int c = pm[j];
        int slot = strip * SLOTS + bp;
        int link = slot, val = -1;
        if (c) {
            int rep = lab[rootof[bp]];         // min border slot of this local root
            link = strip * SLOTS + rep;        // decreasing link (rep <= bp)
            val = link | (c << 23);
        }
        g_uf[slot] = link;                     // coalesced
        if (bp < WW) g_btop[strip * WW + bp] = val;
        else         g_bbot[strip * WW + (bp - WW)] = val;
    }
    if (tid < 4)      atomicAdd(&g_lroots[tid], rc8[tid]);
    else if (tid < 8) atomicAdd(&g_merged[tid - 4], rc8[tid]);
}

// ---------------- compact global union-find (race-safe compression) ----------------
__device__ __forceinline__ int uf_find_g(int x) {
    int r = x, l = g_uf[r];
    while (l != r) { r = l; l = g_uf[r]; }
    int c = x;
    while (c > r) {
        int n = g_uf[c];
        if (n <= r) break;
        g_uf[c] = r;
        c = n;
    }
    return r;
}
__device__ __forceinline__ bool uf_union_g(int a, int b) {
    while (true) {
        a = uf_find_g(a); b = uf_find_g(b);
        if (a == b) return false;
        if (a < b) { int t = a; a = b; b = t; }
        int old = atomicCAS(&g_uf[a], a, b);
        if (old == a) return true;
        a = old;
    }
}

// ---------------- K3: cross-strip border merge (block-aggregated counters) ----------------
__global__ void __launch_bounds__(512) k_border() {
    __shared__ int s_m[4];
    if (threadIdx.x < 4) s_m[threadIdx.x] = 0;
    __syncthreads();

    int e = blockIdx.x * blockDim.x + threadIdx.x;
    int lane = threadIdx.x & 31;
    int myclass = 0;
    int va = -1, vb = -1;
    if (e < NEDGE) {
        int w  = e % WW;
        int bi = e / WW;
        int img = bi / (STRIPS_PER_IMG - 1);
        int brow = bi - img * (STRIPS_PER_IMG - 1);
        int s = img * STRIPS_PER_IMG + brow;
        va = g_bbot[s * WW + w];
        vb = g_btop[(s + 1) * WW + w];
    }
    int pva = __shfl_up_sync(0xFFFFFFFFu, va, 1);
    int pvb = __shfl_up_sync(0xFFFFFFFFu, vb, 1);
    bool dup = (lane > 0) && (va == pva) && (vb == pvb);
    if (e < NEDGE && !dup && (va | vb) >= 0) {
        int ca = va >> 23;
        if (ca == (vb >> 23)) {
            if (uf_union_g(va & 0x7FFFFF, vb & 0x7FFFFF)) myclass = ca;
        }
    }
    if (myclass) atomicAdd(&s_m[myclass - 1], 1);
    __syncthreads();
    if (threadIdx.x < 4 && s_m[threadIdx.x])
        atomicAdd(&g_merged[threadIdx.x], s_m[threadIdx.x]);
}

// ---------------- K4: scalar assembly ----------------
__global__ void k_final(float* __restrict__ out) {
    if (threadIdx.x != 0 || blockIdx.x != 0) return;

    long long cnt[4][5];
    double spho[4][5], slog[4][5], slog1p[4][5];
    for (int t = 0; t < 4; t++)
        for (int c = 0; c < 5; c++) {
            int k = t * 5 + c;
            cnt[t][c]    = (long long)g_cnt[k];
            spho[t][c]   = g_acc[1][k];
            slog[t][c]   = g_acc[2][k];
            slog1p[t][c] = g_acc[3][k];
        }
    long long cpm[5] = {0,0,0,0,0};
    long long ctm[4] = {0,0,0,0};
    for (int t = 0; t < 4; t++)
        for (int c = 0; c < 5; c++) { cpm[c] += cnt[t][c]; ctm[t] += cnt[t][c]; }

    // exact-f32 emulation of ph class values
    float phv[5] = {0.f,0.f,0.f,0.f,0.f};
    int last_i = 1;
    for (int v = 1; v < 5; v++) {
        bool present = (cpm[v] > 0);
        int has_bg = (cpm[v] < (long long)NPIX) ? 1 : 0;
        int nc = g_lroots[v - 1] - g_merged[v - 1];
        int wrapped = (int)((unsigned int)nc * (unsigned int)last_i);
        float s = (float)wrapped;
        if (present) {
            #pragma unroll
            for (int c = 0; c < 5; c++) {
                float ind = (c == v) ? 1.0f : 0.0f;
                float inc = ind + s;
                phv[c] = phv[c] + inc;
            }
            last_i += nc + has_bg;
        }
    }

    const double Nd = (double)NPIX;
    const double LOG_EPS     = -16.1180956392722239;
    const double LOG_ONEM    = -1.1920929665620861e-07;
    const double LOG1P_NEPS  = -1.0000000616860977e-07;
    const double LOG1P_NONEM = -15.9423851528787421;

    double res = 0.0;

    { // term 0: bce_dice(pm==0, tm==0)
        long long n00 = cnt[0][0];
        long long np0 = cpm[0];
        long long nt0 = ctm[0];
        double bsum = (double)n00 * LOG_ONEM
                    + (double)(nt0 - n00) * LOG_EPS
                    + (double)(np0 - n00) * LOG1P_NONEM
                    + (double)((long long)NPIX - nt0 - np0 + n00) * LOG1P_NEPS;
        double bce = -bsum / Nd;
        double dice = 1.0 - (2.0 * (double)n00 + 1.0) / ((double)np0 + (double)nt0 + 1.0);
        res += bce + dice;
    }

    for (int t = 1; t < NTC; t++) {
        long long nt = ctm[t];
        if (nt <= 0) continue;

        int ord[5] = {0,1,2,3,4};
        for (int i = 1; i < 5; i++) {
            int o = ord[i]; float v = phv[o]; int j = i - 1;
            while (j >= 0 && phv[ord[j]] > v) { ord[j+1] = ord[j]; j--; }
            ord[j+1] = o;
        }
        long long kk = (nt - 1) / 2;
        float med = phv[ord[4]];
        long long cum = 0;
        for (int j = 0; j < 5; j++) {
            cum += cnt[t][ord[j]];
            if (cum > kk) { med = phv[ord[j]]; break; }
        }
        bool sel[5];
        #pragma unroll
        for (int c = 0; c < 5; c++) sel[c] = (phv[c] == med);

        double bsum = 0.0, sum_p = 0.0, inter = 0.0, extra_sum = 0.0;
        for (int c = 0; c < 5; c++) {
            if (sel[c]) {
                bsum += slog[t][c];
                inter += spho[t][c];
                for (int tt = 0; tt < 4; tt++) {
                    sum_p += spho[tt][c];
                    if (tt != t) bsum += slog1p[tt][c];
                }
            } else {
                bsum += (double)cnt[t][c] * LOG_EPS;
                extra_sum += spho[t][c];
                for (int tt = 0; tt < 4; tt++)
                    if (tt != t) bsum += (double)cnt[tt][c] * LOG1P_NEPS;
            }
        }
        double bce = -bsum / Nd;
        double dice = 1.0 - (2.0 * inter + 1.0) / (sum_p + (double)nt + 1.0);
        double extra = extra_sum / (double)(nt > 0 ? nt : 1);
        res += bce + dice + extra;
    }

    int nu = 0;
    for (int t = 0; t < NTC; t++) if (ctm[t] > 0) nu++;
    out[0] = (float)(res / (double)(2 * nu + 1));
}

// ---------------- launch ----------------
extern "C" void kernel_launch(void* const* d_in, const int* in_sizes, int n_in,
                              void* d_out, int out_size) {
    const float* pred = (const float*)d_in[0];
    const int*   tm   = (const int*)d_in[1];
    float* out = (float*)d_out;
    (void)in_sizes; (void)n_in; (void)out_size;

    k_zero<<<1, 96>>>();                       // slot 1
    k_stats<<<888, 128>>>(pred, tm);           // slot 2
    k_ccl<<<NSTRIP, 256>>>();                  // slot 3
    k_border<<<(NEDGE + 511) / 512, 512>>>();  // slot 4 — profiled this round
    k_final<<<1, 1>>>(out);                    // slot 5
}